// round 6
// baseline (speedup 1.0000x reference)
#include <cuda_runtime.h>
#include <cuda_bf16.h>
#include <cstdint>

// EnhancedMoEModel: out[b] = sum_e probs[b,e] * sigmoid( relu( relu(x W1e + b1e) W2e + b2e ) W3e + b3e )
// B=524288, D=32, H=64, H2=32, E=8, O=1.
//
// R5: occupancy push. R3 analysis showed issue==tensor==44% with only 16 warps/SM
// (regs=107 blocked the 3rd CTA). Force 3 CTAs/SM via __launch_bounds__(256,3)
// (caps regs at 84, small spills land in L1-cached local) + grid 444 (3/SM).

#define NUM_E 8
// sW1u4 2048 uint4 + sW2u4 2048 uint4 + sWB2 128 float4 + sB1 512 f + sB3 8 f
#define SMEM_BYTES (2048*16 + 2048*16 + 128*16 + 512*4 + 8*4)

__device__ __forceinline__ uint32_t packbf(float lo, float hi) {
    __nv_bfloat162 h = __floats2bfloat162_rn(lo, hi);
    return *reinterpret_cast<uint32_t*>(&h);
}

// pack two f32 to bf16x2, then relu in bf16 (identical to relu-then-pack)
__device__ __forceinline__ uint32_t packbf_relu(float lo, float hi) {
    __nv_bfloat162 h = __floats2bfloat162_rn(lo, hi);
    __nv_bfloat162 z = __floats2bfloat162_rn(0.f, 0.f);
    h = __hmax2(h, z);
    return *reinterpret_cast<uint32_t*>(&h);
}

__device__ __forceinline__ void mma16816(float d[4], const uint32_t a[4], uint32_t b0, uint32_t b1) {
    asm volatile(
        "mma.sync.aligned.m16n8k16.row.col.f32.bf16.bf16.f32 "
        "{%0,%1,%2,%3}, {%4,%5,%6,%7}, {%8,%9}, {%0,%1,%2,%3};\n"
        : "+f"(d[0]), "+f"(d[1]), "+f"(d[2]), "+f"(d[3])
        : "r"(a[0]), "r"(a[1]), "r"(a[2]), "r"(a[3]), "r"(b0), "r"(b1));
}

__global__ void __launch_bounds__(256, 3)
moe_kernel(const float* __restrict__ x,
           const float* __restrict__ probs,
           const float* __restrict__ W1, const float* __restrict__ b1,
           const float* __restrict__ W2, const float* __restrict__ b2,
           const float* __restrict__ W3, const float* __restrict__ b3,
           float* __restrict__ out, int NT32)
{
    extern __shared__ unsigned char smem_raw[];
    uint4*  sW1 = reinterpret_cast<uint4*>(smem_raw);           // 2048 (32 KB): [e][j][lane] = {B(s0), B(s1)}
    uint4*  sW2 = sW1 + 2048;                                   // 2048 (32 KB): [e][j2][half][lane] = {C(2h), C(2h+1)}
    float4* sWB2 = reinterpret_cast<float4*>(sW2 + 2048);       // 128: [e][j2][c] = {w0,w1,b0,b1}
    float*  sB1 = reinterpret_cast<float*>(sWB2 + 128);         // 512
    float*  sB3 = sB1 + 512;                                    // 8

    // ---- one-time weight pre-swizzle into mma B-fragment order (bf16x2 pairs) ----
    // B fragment (m16n8k16, col): lane t: b0={B[2c][n],B[2c+1][n]}, b1={B[2c+8][n],B[2c+9][n]},
    // c=t%4, n=t/4. k-step s adds 16 to k.
    for (int idx = threadIdx.x; idx < 2048; idx += blockDim.x) {
        int lanei = idx & 31, j = (idx >> 5) & 7, e = idx >> 8;
        int cc = lanei & 3, nn = lanei >> 2;
        int col = 8 * j + nn;
        const float* base = W1 + (size_t)e * 32 * 64;
        uint32_t v[2];
        #pragma unroll
        for (int s = 0; s < 2; s++) {
            int k0 = 16 * s + 2 * cc;
            float v00 = base[(k0    ) * 64 + col];
            float v01 = base[(k0 + 1) * 64 + col];
            float v10 = base[(k0 + 8) * 64 + col];
            float v11 = base[(k0 + 9) * 64 + col];
            v[0] = packbf(v00, v01);
            v[1] = packbf(v10, v11);
            if (s == 0) { sW1[idx].x = v[0]; sW1[idx].y = v[1]; }
            else        { sW1[idx].z = v[0]; sW1[idx].w = v[1]; }
        }
    }
    for (int idx = threadIdx.x; idx < 2048; idx += blockDim.x) {
        int lanei = idx & 31, half = (idx >> 5) & 1, j2 = (idx >> 6) & 3, e = idx >> 8;
        int cc = lanei & 3, nn = lanei >> 2;
        int col = 8 * j2 + nn;
        const float* base = W2 + (size_t)e * 64 * 32;
        uint4 outv;
        #pragma unroll
        for (int t = 0; t < 2; t++) {
            int s2 = 2 * half + t;
            int k0 = 16 * s2 + 2 * cc;
            float v00 = base[(k0    ) * 32 + col];
            float v01 = base[(k0 + 1) * 32 + col];
            float v10 = base[(k0 + 8) * 32 + col];
            float v11 = base[(k0 + 9) * 32 + col];
            if (t == 0) { outv.x = packbf(v00, v01); outv.y = packbf(v10, v11); }
            else        { outv.z = packbf(v00, v01); outv.w = packbf(v10, v11); }
        }
        sW2[idx] = outv;
    }
    for (int idx = threadIdx.x; idx < 128; idx += blockDim.x) {
        int cc = idx & 3, j2 = (idx >> 2) & 3, e = idx >> 4;
        int col = 8 * j2 + 2 * cc;
        sWB2[idx] = make_float4(W3[e * 32 + col], W3[e * 32 + col + 1],
                                b2[e * 32 + col], b2[e * 32 + col + 1]);
    }
    for (int idx = threadIdx.x; idx < 512; idx += blockDim.x) sB1[idx] = b1[idx];
    if (threadIdx.x < 8) sB3[threadIdx.x] = b3[threadIdx.x];
    __syncthreads();

    const int lane = threadIdx.x & 31;
    const int c = lane & 3;       // quad column index
    const int rq = lane >> 2;     // row within 8-row group
    const int warp_global = blockIdx.x * 8 + (threadIdx.x >> 5);
    const int nwarps = gridDim.x * 8;

    for (int tile = warp_global; tile < NT32; tile += nwarps) {
        const int rowbase = tile << 5;

        // ---- load x A-fragments for 2 subtiles (f32 -> bf16x2 on the fly) ----
        uint32_t xa[2][2][4];
        #pragma unroll
        for (int r = 0; r < 2; r++) {
            const float* xr0 = x + (size_t)(rowbase + r * 16 + rq) * 32;
            const float* xr1 = xr0 + 8 * 32;
            #pragma unroll
            for (int s = 0; s < 2; s++) {
                const int col = 16 * s + 2 * c;
                float2 v00 = *reinterpret_cast<const float2*>(xr0 + col);
                float2 v10 = *reinterpret_cast<const float2*>(xr1 + col);
                float2 v01 = *reinterpret_cast<const float2*>(xr0 + col + 8);
                float2 v11 = *reinterpret_cast<const float2*>(xr1 + col + 8);
                xa[r][s][0] = packbf(v00.x, v00.y);
                xa[r][s][1] = packbf(v10.x, v10.y);
                xa[r][s][2] = packbf(v01.x, v01.y);
                xa[r][s][3] = packbf(v11.x, v11.y);
            }
        }

        float oa[2][2];
        oa[0][0] = oa[0][1] = oa[1][0] = oa[1][1] = 0.f;

        #pragma unroll 1
        for (int e = 0; e < NUM_E; e++) {
            // ---- layer 1: [32,32] @ [32,64], one LDS.128 per j covers both k-steps ----
            uint32_t ha[2][4][4];
            const uint4* w1e = sW1 + e * 256 + lane;
            #pragma unroll
            for (int j = 0; j < 8; j++) {
                uint4 B = w1e[j * 32];
                float2 bb = *reinterpret_cast<const float2*>(sB1 + e * 64 + 8 * j + 2 * c);
                const int s2 = j >> 1, h = j & 1;
                #pragma unroll
                for (int r = 0; r < 2; r++) {
                    float a[4] = {bb.x, bb.y, bb.x, bb.y};   // bias folded into acc init
                    mma16816(a, xa[r][0], B.x, B.y);
                    mma16816(a, xa[r][1], B.z, B.w);
                    ha[r][s2][h * 2 + 0] = packbf_relu(a[0], a[1]);
                    ha[r][s2][h * 2 + 1] = packbf_relu(a[2], a[3]);
                }
            }

            // ---- layer 2: [32,64] @ [64,32], two LDS.128 per j2 cover 4 k-steps ----
            float p[2][2];
            p[0][0] = p[0][1] = p[1][0] = p[1][1] = 0.f;
            const uint4* w2e = sW2 + e * 256 + lane;
            #pragma unroll
            for (int j2 = 0; j2 < 4; j2++) {
                uint4 Ca = w2e[(j2 * 2 + 0) * 32];   // s2 = 0,1
                uint4 Cb = w2e[(j2 * 2 + 1) * 32];   // s2 = 2,3
                float4 wb = sWB2[(e * 4 + j2) * 4 + c];   // {w0,w1,b0,b1}
                #pragma unroll
                for (int r = 0; r < 2; r++) {
                    float a2[4] = {wb.z, wb.w, wb.z, wb.w};
                    mma16816(a2, ha[r][0], Ca.x, Ca.y);
                    mma16816(a2, ha[r][1], Ca.z, Ca.w);
                    mma16816(a2, ha[r][2], Cb.x, Cb.y);
                    mma16816(a2, ha[r][3], Cb.z, Cb.w);
                    p[r][0] += fmaxf(a2[0], 0.f) * wb.x + fmaxf(a2[1], 0.f) * wb.y;
                    p[r][1] += fmaxf(a2[2], 0.f) * wb.x + fmaxf(a2[3], 0.f) * wb.y;
                }
            }

            // ---- layer 3: quad reduce + sigmoid + prob-weighted accumulate ----
            #pragma unroll
            for (int r = 0; r < 2; r++) {
                p[r][0] += __shfl_xor_sync(0xffffffffu, p[r][0], 1);
                p[r][0] += __shfl_xor_sync(0xffffffffu, p[r][0], 2);
                p[r][1] += __shfl_xor_sync(0xffffffffu, p[r][1], 1);
                p[r][1] += __shfl_xor_sync(0xffffffffu, p[r][1], 2);
            }
            float b3e = sB3[e];
            if (c == 0) {
                #pragma unroll
                for (int r = 0; r < 2; r++) {
                    float z0 = p[r][0] + b3e;
                    float z1 = p[r][1] + b3e;
                    float s0 = 1.f / (1.f + __expf(-z0));
                    float s1 = 1.f / (1.f + __expf(-z1));
                    oa[r][0] += s0 * probs[(size_t)(rowbase + r * 16 + rq) * NUM_E + e];
                    oa[r][1] += s1 * probs[(size_t)(rowbase + r * 16 + 8 + rq) * NUM_E + e];
                }
            }
        }

        if (c == 0) {
            #pragma unroll
            for (int r = 0; r < 2; r++) {
                out[rowbase + r * 16 + rq]     = oa[r][0];
                out[rowbase + r * 16 + 8 + rq] = oa[r][1];
            }
        }
    }
}

extern "C" void kernel_launch(void* const* d_in, const int* in_sizes, int n_in,
                              void* d_out, int out_size) {
    const float* x     = (const float*)d_in[0];
    const float* probs = (const float*)d_in[1];
    const float* W1    = (const float*)d_in[2];
    const float* b1    = (const float*)d_in[3];
    const float* W2    = (const float*)d_in[4];
    const float* b2    = (const float*)d_in[5];
    const float* W3    = (const float*)d_in[6];
    const float* b3    = (const float*)d_in[7];
    float* out = (float*)d_out;

    const int B    = in_sizes[0] / 32;
    const int NT32 = B / 32;   // 16384 warp-tiles of 32 rows

    cudaFuncSetAttribute(moe_kernel, cudaFuncAttributeMaxDynamicSharedMemorySize, SMEM_BYTES);
    cudaFuncSetAttribute(moe_kernel, cudaFuncAttributePreferredSharedMemoryCarveout, 100);

    // 444 persistent CTAs (3 per SM), 3552 warps striding over 16384 tiles
    moe_kernel<<<444, 256, SMEM_BYTES>>>(x, probs, W1, b1, W2, b2, W3, b3, out, NT32);
}

// round 7
// speedup vs baseline: 1.1143x; 1.1143x over previous
#include <cuda_runtime.h>
#include <cuda_bf16.h>
#include <cstdint>

// EnhancedMoEModel: out[b] = sum_e probs[b,e] * sigmoid( relu( relu(x W1e + b1e) W2e + b2e ) W3e + b3e )
// B=524288, D=32, H=64, H2=32, E=8, O=1.
//
// R6: occupancy WITHOUT spills. R5 showed forcing 3x256 spills (regs 80, L2 32%).
// Instead: 3 CTAs x 192 threads (576 thr/SM, reg cap 113 >= our 107) = 18 warps/SM.
// Plus: layer-2 HMMA chain split 4 -> 2+2 (independent accumulators, FADD merge)
// to double ILP in the longest dependency chain.

#define NUM_E 8
// sW1u4 2048 uint4 + sW2u4 2048 uint4 + sWB2 128 float4 + sB1 512 f + sB3 8 f
#define SMEM_BYTES (2048*16 + 2048*16 + 128*16 + 512*4 + 8*4)

__device__ __forceinline__ uint32_t packbf(float lo, float hi) {
    __nv_bfloat162 h = __floats2bfloat162_rn(lo, hi);
    return *reinterpret_cast<uint32_t*>(&h);
}

// pack two f32 to bf16x2, then relu in bf16 (identical to relu-then-pack)
__device__ __forceinline__ uint32_t packbf_relu(float lo, float hi) {
    __nv_bfloat162 h = __floats2bfloat162_rn(lo, hi);
    __nv_bfloat162 z = __floats2bfloat162_rn(0.f, 0.f);
    h = __hmax2(h, z);
    return *reinterpret_cast<uint32_t*>(&h);
}

__device__ __forceinline__ void mma16816(float d[4], const uint32_t a[4], uint32_t b0, uint32_t b1) {
    asm volatile(
        "mma.sync.aligned.m16n8k16.row.col.f32.bf16.bf16.f32 "
        "{%0,%1,%2,%3}, {%4,%5,%6,%7}, {%8,%9}, {%0,%1,%2,%3};\n"
        : "+f"(d[0]), "+f"(d[1]), "+f"(d[2]), "+f"(d[3])
        : "r"(a[0]), "r"(a[1]), "r"(a[2]), "r"(a[3]), "r"(b0), "r"(b1));
}

__global__ void __launch_bounds__(192, 3)
moe_kernel(const float* __restrict__ x,
           const float* __restrict__ probs,
           const float* __restrict__ W1, const float* __restrict__ b1,
           const float* __restrict__ W2, const float* __restrict__ b2,
           const float* __restrict__ W3, const float* __restrict__ b3,
           float* __restrict__ out, int NT32)
{
    extern __shared__ unsigned char smem_raw[];
    uint4*  sW1 = reinterpret_cast<uint4*>(smem_raw);           // 2048 (32 KB): [e][j][lane] = {B(s0), B(s1)}
    uint4*  sW2 = sW1 + 2048;                                   // 2048 (32 KB): [e][j2][half][lane] = {C(2h), C(2h+1)}
    float4* sWB2 = reinterpret_cast<float4*>(sW2 + 2048);       // 128: [e][j2][c] = {w0,w1,b0,b1}
    float*  sB1 = reinterpret_cast<float*>(sWB2 + 128);         // 512
    float*  sB3 = sB1 + 512;                                    // 8

    // ---- one-time weight pre-swizzle into mma B-fragment order (bf16x2 pairs) ----
    // B fragment (m16n8k16, col): lane t: b0={B[2c][n],B[2c+1][n]}, b1={B[2c+8][n],B[2c+9][n]},
    // c=t%4, n=t/4. k-step s adds 16 to k.
    for (int idx = threadIdx.x; idx < 2048; idx += blockDim.x) {
        int lanei = idx & 31, j = (idx >> 5) & 7, e = idx >> 8;
        int cc = lanei & 3, nn = lanei >> 2;
        int col = 8 * j + nn;
        const float* base = W1 + (size_t)e * 32 * 64;
        uint32_t v[2];
        #pragma unroll
        for (int s = 0; s < 2; s++) {
            int k0 = 16 * s + 2 * cc;
            float v00 = base[(k0    ) * 64 + col];
            float v01 = base[(k0 + 1) * 64 + col];
            float v10 = base[(k0 + 8) * 64 + col];
            float v11 = base[(k0 + 9) * 64 + col];
            v[0] = packbf(v00, v01);
            v[1] = packbf(v10, v11);
            if (s == 0) { sW1[idx].x = v[0]; sW1[idx].y = v[1]; }
            else        { sW1[idx].z = v[0]; sW1[idx].w = v[1]; }
        }
    }
    for (int idx = threadIdx.x; idx < 2048; idx += blockDim.x) {
        int lanei = idx & 31, half = (idx >> 5) & 1, j2 = (idx >> 6) & 3, e = idx >> 8;
        int cc = lanei & 3, nn = lanei >> 2;
        int col = 8 * j2 + nn;
        const float* base = W2 + (size_t)e * 64 * 32;
        uint4 outv;
        #pragma unroll
        for (int t = 0; t < 2; t++) {
            int s2 = 2 * half + t;
            int k0 = 16 * s2 + 2 * cc;
            float v00 = base[(k0    ) * 32 + col];
            float v01 = base[(k0 + 1) * 32 + col];
            float v10 = base[(k0 + 8) * 32 + col];
            float v11 = base[(k0 + 9) * 32 + col];
            if (t == 0) { outv.x = packbf(v00, v01); outv.y = packbf(v10, v11); }
            else        { outv.z = packbf(v00, v01); outv.w = packbf(v10, v11); }
        }
        sW2[idx] = outv;
    }
    for (int idx = threadIdx.x; idx < 128; idx += blockDim.x) {
        int cc = idx & 3, j2 = (idx >> 2) & 3, e = idx >> 4;
        int col = 8 * j2 + 2 * cc;
        sWB2[idx] = make_float4(W3[e * 32 + col], W3[e * 32 + col + 1],
                                b2[e * 32 + col], b2[e * 32 + col + 1]);
    }
    for (int idx = threadIdx.x; idx < 512; idx += blockDim.x) sB1[idx] = b1[idx];
    if (threadIdx.x < 8) sB3[threadIdx.x] = b3[threadIdx.x];
    __syncthreads();

    const int lane = threadIdx.x & 31;
    const int c = lane & 3;       // quad column index
    const int rq = lane >> 2;     // row within 8-row group
    const int warp_global = blockIdx.x * 6 + (threadIdx.x >> 5);
    const int nwarps = gridDim.x * 6;

    for (int tile = warp_global; tile < NT32; tile += nwarps) {
        const int rowbase = tile << 5;

        // ---- load x A-fragments for 2 subtiles (f32 -> bf16x2 on the fly) ----
        uint32_t xa[2][2][4];
        #pragma unroll
        for (int r = 0; r < 2; r++) {
            const float* xr0 = x + (size_t)(rowbase + r * 16 + rq) * 32;
            const float* xr1 = xr0 + 8 * 32;
            #pragma unroll
            for (int s = 0; s < 2; s++) {
                const int col = 16 * s + 2 * c;
                float2 v00 = *reinterpret_cast<const float2*>(xr0 + col);
                float2 v10 = *reinterpret_cast<const float2*>(xr1 + col);
                float2 v01 = *reinterpret_cast<const float2*>(xr0 + col + 8);
                float2 v11 = *reinterpret_cast<const float2*>(xr1 + col + 8);
                xa[r][s][0] = packbf(v00.x, v00.y);
                xa[r][s][1] = packbf(v10.x, v10.y);
                xa[r][s][2] = packbf(v01.x, v01.y);
                xa[r][s][3] = packbf(v11.x, v11.y);
            }
        }

        float oa[2][2];
        oa[0][0] = oa[0][1] = oa[1][0] = oa[1][1] = 0.f;

        #pragma unroll 1
        for (int e = 0; e < NUM_E; e++) {
            // ---- layer 1: [32,32] @ [32,64], one LDS.128 per j covers both k-steps ----
            uint32_t ha[2][4][4];
            const uint4* w1e = sW1 + e * 256 + lane;
            #pragma unroll
            for (int j = 0; j < 8; j++) {
                uint4 B = w1e[j * 32];
                float2 bb = *reinterpret_cast<const float2*>(sB1 + e * 64 + 8 * j + 2 * c);
                const int s2 = j >> 1, h = j & 1;
                #pragma unroll
                for (int r = 0; r < 2; r++) {
                    float a[4] = {bb.x, bb.y, bb.x, bb.y};   // bias folded into acc init
                    mma16816(a, xa[r][0], B.x, B.y);
                    mma16816(a, xa[r][1], B.z, B.w);
                    ha[r][s2][h * 2 + 0] = packbf_relu(a[0], a[1]);
                    ha[r][s2][h * 2 + 1] = packbf_relu(a[2], a[3]);
                }
            }

            // ---- layer 2: [32,64] @ [64,32], split 4-chain into 2+2 for ILP ----
            float p[2][2];
            p[0][0] = p[0][1] = p[1][0] = p[1][1] = 0.f;
            const uint4* w2e = sW2 + e * 256 + lane;
            #pragma unroll
            for (int j2 = 0; j2 < 4; j2++) {
                uint4 Ca = w2e[(j2 * 2 + 0) * 32];   // s2 = 0,1
                uint4 Cb = w2e[(j2 * 2 + 1) * 32];   // s2 = 2,3
                float4 wb = sWB2[(e * 4 + j2) * 4 + c];   // {w0,w1,b0,b1}
                #pragma unroll
                for (int r = 0; r < 2; r++) {
                    float a2[4] = {wb.z, wb.w, wb.z, wb.w};
                    float a3[4] = {0.f, 0.f, 0.f, 0.f};
                    mma16816(a2, ha[r][0], Ca.x, Ca.y);
                    mma16816(a3, ha[r][2], Cb.x, Cb.y);
                    mma16816(a2, ha[r][1], Ca.z, Ca.w);
                    mma16816(a3, ha[r][3], Cb.z, Cb.w);
                    p[r][0] += fmaxf(a2[0] + a3[0], 0.f) * wb.x + fmaxf(a2[1] + a3[1], 0.f) * wb.y;
                    p[r][1] += fmaxf(a2[2] + a3[2], 0.f) * wb.x + fmaxf(a2[3] + a3[3], 0.f) * wb.y;
                }
            }

            // ---- layer 3: quad reduce + sigmoid + prob-weighted accumulate ----
            #pragma unroll
            for (int r = 0; r < 2; r++) {
                p[r][0] += __shfl_xor_sync(0xffffffffu, p[r][0], 1);
                p[r][0] += __shfl_xor_sync(0xffffffffu, p[r][0], 2);
                p[r][1] += __shfl_xor_sync(0xffffffffu, p[r][1], 1);
                p[r][1] += __shfl_xor_sync(0xffffffffu, p[r][1], 2);
            }
            float b3e = sB3[e];
            if (c == 0) {
                #pragma unroll
                for (int r = 0; r < 2; r++) {
                    float z0 = p[r][0] + b3e;
                    float z1 = p[r][1] + b3e;
                    float s0 = 1.f / (1.f + __expf(-z0));
                    float s1 = 1.f / (1.f + __expf(-z1));
                    oa[r][0] += s0 * probs[(size_t)(rowbase + r * 16 + rq) * NUM_E + e];
                    oa[r][1] += s1 * probs[(size_t)(rowbase + r * 16 + 8 + rq) * NUM_E + e];
                }
            }
        }

        if (c == 0) {
            #pragma unroll
            for (int r = 0; r < 2; r++) {
                out[rowbase + r * 16 + rq]     = oa[r][0];
                out[rowbase + r * 16 + 8 + rq] = oa[r][1];
            }
        }
    }
}

extern "C" void kernel_launch(void* const* d_in, const int* in_sizes, int n_in,
                              void* d_out, int out_size) {
    const float* x     = (const float*)d_in[0];
    const float* probs = (const float*)d_in[1];
    const float* W1    = (const float*)d_in[2];
    const float* b1    = (const float*)d_in[3];
    const float* W2    = (const float*)d_in[4];
    const float* b2    = (const float*)d_in[5];
    const float* W3    = (const float*)d_in[6];
    const float* b3    = (const float*)d_in[7];
    float* out = (float*)d_out;

    const int B    = in_sizes[0] / 32;
    const int NT32 = B / 32;   // 16384 warp-tiles of 32 rows

    cudaFuncSetAttribute(moe_kernel, cudaFuncAttributeMaxDynamicSharedMemorySize, SMEM_BYTES);
    cudaFuncSetAttribute(moe_kernel, cudaFuncAttributePreferredSharedMemoryCarveout, 100);

    // 444 persistent CTAs (3 per SM) x 6 warps = 2664 warps striding over 16384 tiles
    moe_kernel<<<444, 192, SMEM_BYTES>>>(x, probs, W1, b1, W2, b2, W3, b3, out, NT32);
}

// round 9
// speedup vs baseline: 1.1476x; 1.0300x over previous
#include <cuda_runtime.h>
#include <cuda_bf16.h>
#include <cstdint>

// EnhancedMoEModel: out[b] = sum_e probs[b,e] * sigmoid( relu( relu(x W1e + b1e) W2e + b2e ) W3e + b3e )
// B=524288, D=32, H=64, H2=32, E=8, O=1.
//
// R7: r=1 tiles (16 rows/warp, ~70 regs true footprint) + __launch_bounds__(256,3)
// -> 3 CTAs x 256 = 24 warps/SM with NO spills (cap 85 > footprint, unlike R5).
// Keeps all R3 instruction-diet wins: uint4 LDS.128 fragments, bf16x2 hmax2 relu,
// fused W3/b2 float4, bias folded into accumulator init.

#define NUM_E 8
// sW1u4 2048 uint4 + sW2u4 2048 uint4 + sWB2 128 float4 + sB1 512 f + sB3 8 f
#define SMEM_BYTES (2048*16 + 2048*16 + 128*16 + 512*4 + 8*4)

__device__ __forceinline__ uint32_t packbf(float lo, float hi) {
    __nv_bfloat162 h = __floats2bfloat162_rn(lo, hi);
    return *reinterpret_cast<uint32_t*>(&h);
}

// pack two f32 to bf16x2, then relu in bf16 (identical to relu-then-pack)
__device__ __forceinline__ uint32_t packbf_relu(float lo, float hi) {
    __nv_bfloat162 h = __floats2bfloat162_rn(lo, hi);
    __nv_bfloat162 z = __floats2bfloat162_rn(0.f, 0.f);
    h = __hmax2(h, z);
    return *reinterpret_cast<uint32_t*>(&h);
}

__device__ __forceinline__ void mma16816(float d[4], const uint32_t a[4], uint32_t b0, uint32_t b1) {
    asm volatile(
        "mma.sync.aligned.m16n8k16.row.col.f32.bf16.bf16.f32 "
        "{%0,%1,%2,%3}, {%4,%5,%6,%7}, {%8,%9}, {%0,%1,%2,%3};\n"
        : "+f"(d[0]), "+f"(d[1]), "+f"(d[2]), "+f"(d[3])
        : "r"(a[0]), "r"(a[1]), "r"(a[2]), "r"(a[3]), "r"(b0), "r"(b1));
}

__global__ void __launch_bounds__(256, 3)
moe_kernel(const float* __restrict__ x,
           const float* __restrict__ probs,
           const float* __restrict__ W1, const float* __restrict__ b1,
           const float* __restrict__ W2, const float* __restrict__ b2,
           const float* __restrict__ W3, const float* __restrict__ b3,
           float* __restrict__ out, int NT16)
{
    extern __shared__ unsigned char smem_raw[];
    uint4*  sW1 = reinterpret_cast<uint4*>(smem_raw);           // 2048 (32 KB): [e][j][lane] = {B(s0), B(s1)}
    uint4*  sW2 = sW1 + 2048;                                   // 2048 (32 KB): [e][j2][half][lane] = {C(2h), C(2h+1)}
    float4* sWB2 = reinterpret_cast<float4*>(sW2 + 2048);       // 128: [e][j2][c] = {w0,w1,b0,b1}
    float*  sB1 = reinterpret_cast<float*>(sWB2 + 128);         // 512
    float*  sB3 = sB1 + 512;                                    // 8

    // ---- one-time weight pre-swizzle into mma B-fragment order (bf16x2 pairs) ----
    // B fragment (m16n8k16, col): lane t: b0={B[2c][n],B[2c+1][n]}, b1={B[2c+8][n],B[2c+9][n]},
    // c=t%4, n=t/4. k-step s adds 16 to k.
    for (int idx = threadIdx.x; idx < 2048; idx += blockDim.x) {
        int lanei = idx & 31, j = (idx >> 5) & 7, e = idx >> 8;
        int cc = lanei & 3, nn = lanei >> 2;
        int col = 8 * j + nn;
        const float* base = W1 + (size_t)e * 32 * 64;
        #pragma unroll
        for (int s = 0; s < 2; s++) {
            int k0 = 16 * s + 2 * cc;
            float v00 = base[(k0    ) * 64 + col];
            float v01 = base[(k0 + 1) * 64 + col];
            float v10 = base[(k0 + 8) * 64 + col];
            float v11 = base[(k0 + 9) * 64 + col];
            if (s == 0) { sW1[idx].x = packbf(v00, v01); sW1[idx].y = packbf(v10, v11); }
            else        { sW1[idx].z = packbf(v00, v01); sW1[idx].w = packbf(v10, v11); }
        }
    }
    for (int idx = threadIdx.x; idx < 2048; idx += blockDim.x) {
        int lanei = idx & 31, half = (idx >> 5) & 1, j2 = (idx >> 6) & 3, e = idx >> 8;
        int cc = lanei & 3, nn = lanei >> 2;
        int col = 8 * j2 + nn;
        const float* base = W2 + (size_t)e * 64 * 32;
        uint4 outv;
        #pragma unroll
        for (int t = 0; t < 2; t++) {
            int s2 = 2 * half + t;
            int k0 = 16 * s2 + 2 * cc;
            float v00 = base[(k0    ) * 32 + col];
            float v01 = base[(k0 + 1) * 32 + col];
            float v10 = base[(k0 + 8) * 32 + col];
            float v11 = base[(k0 + 9) * 32 + col];
            if (t == 0) { outv.x = packbf(v00, v01); outv.y = packbf(v10, v11); }
            else        { outv.z = packbf(v00, v01); outv.w = packbf(v10, v11); }
        }
        sW2[idx] = outv;
    }
    for (int idx = threadIdx.x; idx < 128; idx += blockDim.x) {
        int cc = idx & 3, j2 = (idx >> 2) & 3, e = idx >> 4;
        int col = 8 * j2 + 2 * cc;
        sWB2[idx] = make_float4(W3[e * 32 + col], W3[e * 32 + col + 1],
                                b2[e * 32 + col], b2[e * 32 + col + 1]);
    }
    for (int idx = threadIdx.x; idx < 512; idx += blockDim.x) sB1[idx] = b1[idx];
    if (threadIdx.x < 8) sB3[threadIdx.x] = b3[threadIdx.x];
    __syncthreads();

    const int lane = threadIdx.x & 31;
    const int c = lane & 3;       // quad column index
    const int rq = lane >> 2;     // row within 8-row group
    const int warp_global = blockIdx.x * 8 + (threadIdx.x >> 5);
    const int nwarps = gridDim.x * 8;

    for (int tile = warp_global; tile < NT16; tile += nwarps) {
        const int rowbase = tile << 4;

        // ---- load x A-fragments (f32 -> bf16x2 on the fly) ----
        uint32_t xa[2][4];
        {
            const float* xr0 = x + (size_t)(rowbase + rq) * 32;
            const float* xr1 = xr0 + 8 * 32;
            #pragma unroll
            for (int s = 0; s < 2; s++) {
                const int col = 16 * s + 2 * c;
                float2 v00 = *reinterpret_cast<const float2*>(xr0 + col);
                float2 v10 = *reinterpret_cast<const float2*>(xr1 + col);
                float2 v01 = *reinterpret_cast<const float2*>(xr0 + col + 8);
                float2 v11 = *reinterpret_cast<const float2*>(xr1 + col + 8);
                xa[s][0] = packbf(v00.x, v00.y);
                xa[s][1] = packbf(v10.x, v10.y);
                xa[s][2] = packbf(v01.x, v01.y);
                xa[s][3] = packbf(v11.x, v11.y);
            }
        }

        float oa0 = 0.f, oa1 = 0.f;

        #pragma unroll 1
        for (int e = 0; e < NUM_E; e++) {
            // ---- layer 1: [16,32] @ [32,64], one LDS.128 per j covers both k-steps ----
            uint32_t ha[4][4];
            const uint4* w1e = sW1 + e * 256 + lane;
            #pragma unroll
            for (int j = 0; j < 8; j++) {
                uint4 B = w1e[j * 32];
                float2 bb = *reinterpret_cast<const float2*>(sB1 + e * 64 + 8 * j + 2 * c);
                const int s2 = j >> 1, h = j & 1;
                float a[4] = {bb.x, bb.y, bb.x, bb.y};   // bias folded into acc init
                mma16816(a, xa[0], B.x, B.y);
                mma16816(a, xa[1], B.z, B.w);
                ha[s2][h * 2 + 0] = packbf_relu(a[0], a[1]);
                ha[s2][h * 2 + 1] = packbf_relu(a[2], a[3]);
            }

            // ---- layer 2: [16,64] @ [64,32], split 4-chain into 2+2 for ILP ----
            float p0 = 0.f, p1 = 0.f;
            const uint4* w2e = sW2 + e * 256 + lane;
            #pragma unroll
            for (int j2 = 0; j2 < 4; j2++) {
                uint4 Ca = w2e[(j2 * 2 + 0) * 32];   // s2 = 0,1
                uint4 Cb = w2e[(j2 * 2 + 1) * 32];   // s2 = 2,3
                float4 wb = sWB2[(e * 4 + j2) * 4 + c];   // {w0,w1,b0,b1}
                float a2[4] = {wb.z, wb.w, wb.z, wb.w};
                float a3[4] = {0.f, 0.f, 0.f, 0.f};
                mma16816(a2, ha[0], Ca.x, Ca.y);
                mma16816(a3, ha[2], Cb.x, Cb.y);
                mma16816(a2, ha[1], Ca.z, Ca.w);
                mma16816(a3, ha[3], Cb.z, Cb.w);
                p0 += fmaxf(a2[0] + a3[0], 0.f) * wb.x + fmaxf(a2[1] + a3[1], 0.f) * wb.y;
                p1 += fmaxf(a2[2] + a3[2], 0.f) * wb.x + fmaxf(a2[3] + a3[3], 0.f) * wb.y;
            }

            // ---- layer 3: quad reduce + sigmoid + prob-weighted accumulate ----
            p0 += __shfl_xor_sync(0xffffffffu, p0, 1);
            p0 += __shfl_xor_sync(0xffffffffu, p0, 2);
            p1 += __shfl_xor_sync(0xffffffffu, p1, 1);
            p1 += __shfl_xor_sync(0xffffffffu, p1, 2);

            if (c == 0) {
                float b3e = sB3[e];
                float z0 = p0 + b3e;
                float z1 = p1 + b3e;
                float s0 = 1.f / (1.f + __expf(-z0));
                float s1 = 1.f / (1.f + __expf(-z1));
                oa0 += s0 * probs[(size_t)(rowbase + rq) * NUM_E + e];
                oa1 += s1 * probs[(size_t)(rowbase + 8 + rq) * NUM_E + e];
            }
        }

        if (c == 0) {
            out[rowbase + rq]     = oa0;
            out[rowbase + 8 + rq] = oa1;
        }
    }
}

extern "C" void kernel_launch(void* const* d_in, const int* in_sizes, int n_in,
                              void* d_out, int out_size) {
    const float* x     = (const float*)d_in[0];
    const float* probs = (const float*)d_in[1];
    const float* W1    = (const float*)d_in[2];
    const float* b1    = (const float*)d_in[3];
    const float* W2    = (const float*)d_in[4];
    const float* b2    = (const float*)d_in[5];
    const float* W3    = (const float*)d_in[6];
    const float* b3    = (const float*)d_in[7];
    float* out = (float*)d_out;

    const int B    = in_sizes[0] / 32;
    const int NT16 = B / 16;   // 32768 warp-tiles of 16 rows

    cudaFuncSetAttribute(moe_kernel, cudaFuncAttributeMaxDynamicSharedMemorySize, SMEM_BYTES);
    cudaFuncSetAttribute(moe_kernel, cudaFuncAttributePreferredSharedMemoryCarveout, 100);

    // 444 persistent CTAs (3 per SM) x 8 warps = 3552 warps over 32768 tiles
    moe_kernel<<<444, 256, SMEM_BYTES>>>(x, probs, W1, b1, W2, b2, W3, b3, out, NT16);
}

// round 10
// speedup vs baseline: 1.3520x; 1.1781x over previous
#include <cuda_runtime.h>
#include <cuda_bf16.h>
#include <cstdint>

// EnhancedMoEModel: out[b] = sum_e probs[b,e] * sigmoid( relu( relu(x W1e + b1e) W2e + b2e ) W3e + b3e )
// B=524288, D=32, H=64, H2=32, E=8, O=1.
//
// R9 (base = R3, best 121.3us): replace layer-3 shuffle-reduction with a third
// chained HMMA (B = w3 in col 0, zeros elsewhere) -> z lands in c==0 lanes of the
// D-fragment directly. Kills 8 SHFL + dot + divergent branch per (expert,tile)
// (~20% of issue stream). Branchless epilogue. __launch_bounds__(256,2).

#define NUM_E 8
// sW1 2048 u4 + sW2 2048 u4 + sW3f 256 u4 + sBB2 128 f2 + sB1 512 f + sB3 8 f
#define SMEM_BYTES (2048*16 + 2048*16 + 256*16 + 128*8 + 512*4 + 8*4)

__device__ __forceinline__ uint32_t packbf(float lo, float hi) {
    __nv_bfloat162 h = __floats2bfloat162_rn(lo, hi);
    return *reinterpret_cast<uint32_t*>(&h);
}

// pack two f32 to bf16x2, then relu in bf16 (identical to relu-then-pack)
__device__ __forceinline__ uint32_t packbf_relu(float lo, float hi) {
    __nv_bfloat162 h = __floats2bfloat162_rn(lo, hi);
    __nv_bfloat162 z = __floats2bfloat162_rn(0.f, 0.f);
    h = __hmax2(h, z);
    return *reinterpret_cast<uint32_t*>(&h);
}

__device__ __forceinline__ void mma16816(float d[4], const uint32_t a[4], uint32_t b0, uint32_t b1) {
    asm volatile(
        "mma.sync.aligned.m16n8k16.row.col.f32.bf16.bf16.f32 "
        "{%0,%1,%2,%3}, {%4,%5,%6,%7}, {%8,%9}, {%0,%1,%2,%3};\n"
        : "+f"(d[0]), "+f"(d[1]), "+f"(d[2]), "+f"(d[3])
        : "r"(a[0]), "r"(a[1]), "r"(a[2]), "r"(a[3]), "r"(b0), "r"(b1));
}

__global__ void __launch_bounds__(256, 2)
moe_kernel(const float* __restrict__ x,
           const float* __restrict__ probs,
           const float* __restrict__ W1, const float* __restrict__ b1,
           const float* __restrict__ W2, const float* __restrict__ b2,
           const float* __restrict__ W3, const float* __restrict__ b3,
           float* __restrict__ out, int NT32)
{
    extern __shared__ unsigned char smem_raw[];
    uint4*  sW1  = reinterpret_cast<uint4*>(smem_raw);          // 2048: [e][j][lane] = {B(s0), B(s1)}
    uint4*  sW2  = sW1 + 2048;                                  // 2048: [e][j2][half][lane]
    uint4*  sW3f = sW2 + 2048;                                  // 256: [e][lane] = L3 B-frags (both k-steps)
    float2* sBB2 = reinterpret_cast<float2*>(sW3f + 256);       // 128: [e][j2][c] = b2 pair
    float*  sB1  = reinterpret_cast<float*>(sBB2 + 128);        // 512
    float*  sB3  = sB1 + 512;                                   // 8

    // ---- one-time weight pre-swizzle into mma B-fragment order (bf16x2 pairs) ----
    // B fragment (m16n8k16, col): lane t: b0={B[2c][n],B[2c+1][n]}, b1={B[2c+8][n],B[2c+9][n]},
    // c=t%4, n=t/4. k-step s adds 16 to k.
    for (int idx = threadIdx.x; idx < 2048; idx += blockDim.x) {
        int lanei = idx & 31, j = (idx >> 5) & 7, e = idx >> 8;
        int cc = lanei & 3, nn = lanei >> 2;
        int col = 8 * j + nn;
        const float* base = W1 + (size_t)e * 32 * 64;
        #pragma unroll
        for (int s = 0; s < 2; s++) {
            int k0 = 16 * s + 2 * cc;
            float v00 = base[(k0    ) * 64 + col];
            float v01 = base[(k0 + 1) * 64 + col];
            float v10 = base[(k0 + 8) * 64 + col];
            float v11 = base[(k0 + 9) * 64 + col];
            if (s == 0) { sW1[idx].x = packbf(v00, v01); sW1[idx].y = packbf(v10, v11); }
            else        { sW1[idx].z = packbf(v00, v01); sW1[idx].w = packbf(v10, v11); }
        }
    }
    for (int idx = threadIdx.x; idx < 2048; idx += blockDim.x) {
        int lanei = idx & 31, half = (idx >> 5) & 1, j2 = (idx >> 6) & 3, e = idx >> 8;
        int cc = lanei & 3, nn = lanei >> 2;
        int col = 8 * j2 + nn;
        const float* base = W2 + (size_t)e * 64 * 32;
        uint4 outv;
        #pragma unroll
        for (int t = 0; t < 2; t++) {
            int s2 = 2 * half + t;
            int k0 = 16 * s2 + 2 * cc;
            float v00 = base[(k0    ) * 32 + col];
            float v01 = base[(k0 + 1) * 32 + col];
            float v10 = base[(k0 + 8) * 32 + col];
            float v11 = base[(k0 + 9) * 32 + col];
            if (t == 0) { outv.x = packbf(v00, v01); outv.y = packbf(v10, v11); }
            else        { outv.z = packbf(v00, v01); outv.w = packbf(v10, v11); }
        }
        sW2[idx] = outv;
    }
    // L3 B-fragments: B[32,8] with col 0 = w3, cols 1..7 = 0.
    // lane (cc,nn): nonzero only for nn==0. uint4 = {b0(s3=0), b1(s3=0), b0(s3=1), b1(s3=1)}
    for (int idx = threadIdx.x; idx < 256; idx += blockDim.x) {
        int lanei = idx & 31, e = idx >> 5;
        int cc = lanei & 3, nn = lanei >> 2;
        uint4 v = make_uint4(0u, 0u, 0u, 0u);
        if (nn == 0) {
            const float* w3 = W3 + e * 32;
            v.x = packbf(w3[2 * cc],      w3[2 * cc + 1]);
            v.y = packbf(w3[2 * cc + 8],  w3[2 * cc + 9]);
            v.z = packbf(w3[2 * cc + 16], w3[2 * cc + 17]);
            v.w = packbf(w3[2 * cc + 24], w3[2 * cc + 25]);
        }
        sW3f[idx] = v;
    }
    for (int idx = threadIdx.x; idx < 128; idx += blockDim.x) {
        int cc = idx & 3, j2 = (idx >> 2) & 3, e = idx >> 4;
        int col = 8 * j2 + 2 * cc;
        sBB2[idx] = make_float2(b2[e * 32 + col], b2[e * 32 + col + 1]);
    }
    for (int idx = threadIdx.x; idx < 512; idx += blockDim.x) sB1[idx] = b1[idx];
    if (threadIdx.x < 8) sB3[threadIdx.x] = b3[threadIdx.x];
    __syncthreads();

    const int lane = threadIdx.x & 31;
    const int c = lane & 3;       // quad column index
    const int rq = lane >> 2;     // row within 8-row group
    const int warp_global = blockIdx.x * 8 + (threadIdx.x >> 5);
    const int nwarps = gridDim.x * 8;

    for (int tile = warp_global; tile < NT32; tile += nwarps) {
        const int rowbase = tile << 5;

        // ---- load x A-fragments for 2 subtiles (f32 -> bf16x2 on the fly) ----
        uint32_t xa[2][2][4];
        #pragma unroll
        for (int r = 0; r < 2; r++) {
            const float* xr0 = x + (size_t)(rowbase + r * 16 + rq) * 32;
            const float* xr1 = xr0 + 8 * 32;
            #pragma unroll
            for (int s = 0; s < 2; s++) {
                const int col = 16 * s + 2 * c;
                float2 v00 = *reinterpret_cast<const float2*>(xr0 + col);
                float2 v10 = *reinterpret_cast<const float2*>(xr1 + col);
                float2 v01 = *reinterpret_cast<const float2*>(xr0 + col + 8);
                float2 v11 = *reinterpret_cast<const float2*>(xr1 + col + 8);
                xa[r][s][0] = packbf(v00.x, v00.y);
                xa[r][s][1] = packbf(v10.x, v10.y);
                xa[r][s][2] = packbf(v01.x, v01.y);
                xa[r][s][3] = packbf(v11.x, v11.y);
            }
        }

        float oa[2][2];
        oa[0][0] = oa[0][1] = oa[1][0] = oa[1][1] = 0.f;

        #pragma unroll 1
        for (int e = 0; e < NUM_E; e++) {
            // ---- layer 1: [32,32] @ [32,64], one LDS.128 per j covers both k-steps ----
            uint32_t ha[2][4][4];
            const uint4* w1e = sW1 + e * 256 + lane;
            #pragma unroll
            for (int j = 0; j < 8; j++) {
                uint4 B = w1e[j * 32];
                float2 bb = *reinterpret_cast<const float2*>(sB1 + e * 64 + 8 * j + 2 * c);
                const int s2 = j >> 1, h = j & 1;
                #pragma unroll
                for (int r = 0; r < 2; r++) {
                    float a[4] = {bb.x, bb.y, bb.x, bb.y};   // bias folded into acc init
                    mma16816(a, xa[r][0], B.x, B.y);
                    mma16816(a, xa[r][1], B.z, B.w);
                    ha[r][s2][h * 2 + 0] = packbf_relu(a[0], a[1]);
                    ha[r][s2][h * 2 + 1] = packbf_relu(a[2], a[3]);
                }
            }

            // ---- layer 2: [32,64] @ [64,32]; outputs repacked into L3 A-fragments ----
            uint32_t la[2][2][4];   // [r][s3][frag]
            const uint4* w2e = sW2 + e * 256 + lane;
            #pragma unroll
            for (int j2 = 0; j2 < 4; j2++) {
                uint4 Ca = w2e[(j2 * 2 + 0) * 32];   // s2 = 0,1
                uint4 Cb = w2e[(j2 * 2 + 1) * 32];   // s2 = 2,3
                float2 bb2 = sBB2[e * 16 + j2 * 4 + c];
                const int s3 = j2 >> 1, h = j2 & 1;
                #pragma unroll
                for (int r = 0; r < 2; r++) {
                    float a2[4] = {bb2.x, bb2.y, bb2.x, bb2.y};
                    mma16816(a2, ha[r][0], Ca.x, Ca.y);
                    mma16816(a2, ha[r][1], Ca.z, Ca.w);
                    mma16816(a2, ha[r][2], Cb.x, Cb.y);
                    mma16816(a2, ha[r][3], Cb.z, Cb.w);
                    la[r][s3][h * 2 + 0] = packbf_relu(a2[0], a2[1]);
                    la[r][s3][h * 2 + 1] = packbf_relu(a2[2], a2[3]);
                }
            }

            // ---- layer 3 as HMMA: z = relu(h2) @ [w3 | 0...]; z in col 0 (c==0 lanes) ----
            uint4 W3v = sW3f[e * 32 + lane];
            float b3e = sB3[e];
            #pragma unroll
            for (int r = 0; r < 2; r++) {
                float d[4] = {b3e, 0.f, b3e, 0.f};
                mma16816(d, la[r][0], W3v.x, W3v.y);
                mma16816(d, la[r][1], W3v.z, W3v.w);
                // d[0] = z(row rq), d[2] = z(row rq+8), valid where c==0; others harmless
                float s0 = 1.f / (1.f + __expf(-d[0]));
                float s1 = 1.f / (1.f + __expf(-d[2]));
                oa[r][0] += s0 * probs[(size_t)(rowbase + r * 16 + rq) * NUM_E + e];
                oa[r][1] += s1 * probs[(size_t)(rowbase + r * 16 + 8 + rq) * NUM_E + e];
            }
        }

        if (c == 0) {
            #pragma unroll
            for (int r = 0; r < 2; r++) {
                out[rowbase + r * 16 + rq]     = oa[r][0];
                out[rowbase + r * 16 + 8 + rq] = oa[r][1];
            }
        }
    }
}

extern "C" void kernel_launch(void* const* d_in, const int* in_sizes, int n_in,
                              void* d_out, int out_size) {
    const float* x     = (const float*)d_in[0];
    const float* probs = (const float*)d_in[1];
    const float* W1    = (const float*)d_in[2];
    const float* b1    = (const float*)d_in[3];
    const float* W2    = (const float*)d_in[4];
    const float* b2    = (const float*)d_in[5];
    const float* W3    = (const float*)d_in[6];
    const float* b3    = (const float*)d_in[7];
    float* out = (float*)d_out;

    const int B    = in_sizes[0] / 32;
    const int NT32 = B / 32;   // 16384 warp-tiles of 32 rows

    cudaFuncSetAttribute(moe_kernel, cudaFuncAttributeMaxDynamicSharedMemorySize, SMEM_BYTES);
    cudaFuncSetAttribute(moe_kernel, cudaFuncAttributePreferredSharedMemoryCarveout, 100);

    // 296 persistent CTAs (2 per SM), 2368 warps striding over 16384 tiles
    moe_kernel<<<296, 256, SMEM_BYTES>>>(x, probs, W1, b1, W2, b2, W3, b3, out, NT32);
}

// round 12
// speedup vs baseline: 1.5201x; 1.1243x over previous
#include <cuda_runtime.h>
#include <cuda_fp16.h>
#include <cstdint>

// EnhancedMoEModel: out[b] = sum_e probs[b,e] * sigmoid( relu( relu(x W1e + b1e) W2e + b2e ) W3e + b3e )
// B=524288, D=32, H=64, H2=32, E=8, O=1.
//
// R10: full f16 pipeline with f16 ACCUMULATION. The f16-acc m16n8k16 D fragment
// (2 packed f16x2 regs) IS the next layer's A fragment: zero CVT/pack anywhere,
// relu = one HMNMX2 per reg. f16 inputs also quantize 8x finer than bf16.
// Keeps R9's L3-as-HMMA (w3 in col 0 of B). 2 CTAs x 256, persistent 296.

#define NUM_E 8
// sW1 2048 u4 + sW2 2048 u4 + sW3f 256 u4 + sB1h 256 u32 + sB2h 128 u32 + sB3h 8 u32
#define SMEM_BYTES (2048*16 + 2048*16 + 256*16 + 256*4 + 128*4 + 8*4)

__device__ __forceinline__ uint32_t packh(float lo, float hi) {
    __half2 h = __floats2half2_rn(lo, hi);
    return *reinterpret_cast<uint32_t*>(&h);
}

__device__ __forceinline__ uint32_t hrelu(uint32_t v) {
    __half2 h = *reinterpret_cast<__half2*>(&v);
    h = __hmax2(h, __floats2half2_rn(0.f, 0.f));
    return *reinterpret_cast<uint32_t*>(&h);
}

// f16-accumulate mma: D (2 regs, f16x2) layout == next-layer A-fragment layout.
__device__ __forceinline__ void mma_f16(uint32_t& d0, uint32_t& d1,
                                        const uint32_t a[4], uint32_t b0, uint32_t b1) {
    asm volatile(
        "mma.sync.aligned.m16n8k16.row.col.f16.f16.f16.f16 "
        "{%0,%1}, {%2,%3,%4,%5}, {%6,%7}, {%0,%1};\n"
        : "+r"(d0), "+r"(d1)
        : "r"(a[0]), "r"(a[1]), "r"(a[2]), "r"(a[3]), "r"(b0), "r"(b1));
}

__global__ void __launch_bounds__(256, 2)
moe_kernel(const float* __restrict__ x,
           const float* __restrict__ probs,
           const float* __restrict__ W1, const float* __restrict__ b1,
           const float* __restrict__ W2, const float* __restrict__ b2,
           const float* __restrict__ W3, const float* __restrict__ b3,
           float* __restrict__ out, int NT32)
{
    extern __shared__ unsigned char smem_raw[];
    uint4*    sW1  = reinterpret_cast<uint4*>(smem_raw);        // 2048: [e][j][lane] = {B(s0), B(s1)}
    uint4*    sW2  = sW1 + 2048;                                // 2048: [e][j2][half][lane]
    uint4*    sW3f = sW2 + 2048;                                // 256: [e][lane] L3 B-frags
    uint32_t* sB1h = reinterpret_cast<uint32_t*>(sW3f + 256);   // 256: [e][j][c] = f16x2 bias pair
    uint32_t* sB2h = sB1h + 256;                                // 128: [e][j2][c]
    uint32_t* sB3h = sB2h + 128;                                // 8:   [e] = f16x2 {b3,b3}

    // ---- one-time weight pre-swizzle into mma B-fragment order (f16x2 pairs) ----
    // B fragment (m16n8k16, col): lane t: b0={B[2c][n],B[2c+1][n]}, b1={B[2c+8][n],B[2c+9][n]},
    // c=t%4, n=t/4. k-step s adds 16 to k.
    for (int idx = threadIdx.x; idx < 2048; idx += blockDim.x) {
        int lanei = idx & 31, j = (idx >> 5) & 7, e = idx >> 8;
        int cc = lanei & 3, nn = lanei >> 2;
        int col = 8 * j + nn;
        const float* base = W1 + (size_t)e * 32 * 64;
        #pragma unroll
        for (int s = 0; s < 2; s++) {
            int k0 = 16 * s + 2 * cc;
            float v00 = base[(k0    ) * 64 + col];
            float v01 = base[(k0 + 1) * 64 + col];
            float v10 = base[(k0 + 8) * 64 + col];
            float v11 = base[(k0 + 9) * 64 + col];
            if (s == 0) { sW1[idx].x = packh(v00, v01); sW1[idx].y = packh(v10, v11); }
            else        { sW1[idx].z = packh(v00, v01); sW1[idx].w = packh(v10, v11); }
        }
    }
    for (int idx = threadIdx.x; idx < 2048; idx += blockDim.x) {
        int lanei = idx & 31, half = (idx >> 5) & 1, j2 = (idx >> 6) & 3, e = idx >> 8;
        int cc = lanei & 3, nn = lanei >> 2;
        int col = 8 * j2 + nn;
        const float* base = W2 + (size_t)e * 64 * 32;
        uint4 outv;
        #pragma unroll
        for (int t = 0; t < 2; t++) {
            int s2 = 2 * half + t;
            int k0 = 16 * s2 + 2 * cc;
            float v00 = base[(k0    ) * 32 + col];
            float v01 = base[(k0 + 1) * 32 + col];
            float v10 = base[(k0 + 8) * 32 + col];
            float v11 = base[(k0 + 9) * 32 + col];
            if (t == 0) { outv.x = packh(v00, v01); outv.y = packh(v10, v11); }
            else        { outv.z = packh(v00, v01); outv.w = packh(v10, v11); }
        }
        sW2[idx] = outv;
    }
    // L3 B-fragments: B[32,8] with col 0 = w3, cols 1..7 = 0 (nonzero only for nn==0).
    for (int idx = threadIdx.x; idx < 256; idx += blockDim.x) {
        int lanei = idx & 31, e = idx >> 5;
        int cc = lanei & 3, nn = lanei >> 2;
        uint4 v = make_uint4(0u, 0u, 0u, 0u);
        if (nn == 0) {
            const float* w3 = W3 + e * 32;
            v.x = packh(w3[2 * cc],      w3[2 * cc + 1]);
            v.y = packh(w3[2 * cc + 8],  w3[2 * cc + 9]);
            v.z = packh(w3[2 * cc + 16], w3[2 * cc + 17]);
            v.w = packh(w3[2 * cc + 24], w3[2 * cc + 25]);
        }
        sW3f[idx] = v;
    }
    for (int idx = threadIdx.x; idx < 256; idx += blockDim.x) {
        int cc = idx & 3, j = (idx >> 2) & 7, e = idx >> 5;
        int col = 8 * j + 2 * cc;
        sB1h[idx] = packh(b1[e * 64 + col], b1[e * 64 + col + 1]);
    }
    for (int idx = threadIdx.x; idx < 128; idx += blockDim.x) {
        int cc = idx & 3, j2 = (idx >> 2) & 3, e = idx >> 4;
        int col = 8 * j2 + 2 * cc;
        sB2h[idx] = packh(b2[e * 32 + col], b2[e * 32 + col + 1]);
    }
    if (threadIdx.x < 8) sB3h[threadIdx.x] = packh(b3[threadIdx.x], b3[threadIdx.x]);
    __syncthreads();

    const int lane = threadIdx.x & 31;
    const int c = lane & 3;       // quad column index
    const int rq = lane >> 2;     // row within 8-row group
    const int warp_global = blockIdx.x * 8 + (threadIdx.x >> 5);
    const int nwarps = gridDim.x * 8;

    for (int tile = warp_global; tile < NT32; tile += nwarps) {
        const int rowbase = tile << 5;

        // ---- load x A-fragments for 2 subtiles (f32 -> f16x2 on the fly) ----
        uint32_t xa[2][2][4];
        #pragma unroll
        for (int r = 0; r < 2; r++) {
            const float* xr0 = x + (size_t)(rowbase + r * 16 + rq) * 32;
            const float* xr1 = xr0 + 8 * 32;
            #pragma unroll
            for (int s = 0; s < 2; s++) {
                const int col = 16 * s + 2 * c;
                float2 v00 = *reinterpret_cast<const float2*>(xr0 + col);
                float2 v10 = *reinterpret_cast<const float2*>(xr1 + col);
                float2 v01 = *reinterpret_cast<const float2*>(xr0 + col + 8);
                float2 v11 = *reinterpret_cast<const float2*>(xr1 + col + 8);
                xa[r][s][0] = packh(v00.x, v00.y);
                xa[r][s][1] = packh(v10.x, v10.y);
                xa[r][s][2] = packh(v01.x, v01.y);
                xa[r][s][3] = packh(v11.x, v11.y);
            }
        }

        float oa[2][2];
        oa[0][0] = oa[0][1] = oa[1][0] = oa[1][1] = 0.f;

        #pragma unroll 1
        for (int e = 0; e < NUM_E; e++) {
            // ---- layer 1: [32,32] @ [32,64]; f16-acc D regs ARE next A-fragments ----
            uint32_t ha[2][4][4];
            const uint4* w1e = sW1 + e * 256 + lane;
            #pragma unroll
            for (int j = 0; j < 8; j++) {
                uint4 B = w1e[j * 32];
                uint32_t bb = sB1h[e * 32 + j * 4 + c];
                const int s2 = j >> 1, h = j & 1;
                #pragma unroll
                for (int r = 0; r < 2; r++) {
                    uint32_t d0 = bb, d1 = bb;   // bias folded into acc init
                    mma_f16(d0, d1, xa[r][0], B.x, B.y);
                    mma_f16(d0, d1, xa[r][1], B.z, B.w);
                    ha[r][s2][h * 2 + 0] = hrelu(d0);
                    ha[r][s2][h * 2 + 1] = hrelu(d1);
                }
            }

            // ---- layer 2: [32,64] @ [64,32]; outputs feed L3 A-fragments directly ----
            uint32_t la[2][2][4];   // [r][s3][frag]
            const uint4* w2e = sW2 + e * 256 + lane;
            #pragma unroll
            for (int j2 = 0; j2 < 4; j2++) {
                uint4 Ca = w2e[(j2 * 2 + 0) * 32];   // s2 = 0,1
                uint4 Cb = w2e[(j2 * 2 + 1) * 32];   // s2 = 2,3
                uint32_t bb2 = sB2h[e * 16 + j2 * 4 + c];
                const int s3 = j2 >> 1, h = j2 & 1;
                #pragma unroll
                for (int r = 0; r < 2; r++) {
                    uint32_t d0 = bb2, d1 = bb2;
                    mma_f16(d0, d1, ha[r][0], Ca.x, Ca.y);
                    mma_f16(d0, d1, ha[r][1], Ca.z, Ca.w);
                    mma_f16(d0, d1, ha[r][2], Cb.x, Cb.y);
                    mma_f16(d0, d1, ha[r][3], Cb.z, Cb.w);
                    la[r][s3][h * 2 + 0] = hrelu(d0);
                    la[r][s3][h * 2 + 1] = hrelu(d1);
                }
            }

            // ---- layer 3 as HMMA: z = relu(h2) @ [w3 | 0...]; z in lo half of D regs ----
            uint4 W3v = sW3f[e * 32 + lane];
            uint32_t b3h = sB3h[e];
            #pragma unroll
            for (int r = 0; r < 2; r++) {
                uint32_t d0 = b3h, d1 = b3h;
                mma_f16(d0, d1, la[r][0], W3v.x, W3v.y);
                mma_f16(d0, d1, la[r][1], W3v.z, W3v.w);
                // d0.lo = z(row rq), d1.lo = z(row rq+8); valid where c==0, others harmless
                float z0 = __low2float(*reinterpret_cast<__half2*>(&d0));
                float z1 = __low2float(*reinterpret_cast<__half2*>(&d1));
                float s0 = 1.f / (1.f + __expf(-z0));
                float s1 = 1.f / (1.f + __expf(-z1));
                oa[r][0] += s0 * probs[(size_t)(rowbase + r * 16 + rq) * NUM_E + e];
                oa[r][1] += s1 * probs[(size_t)(rowbase + r * 16 + 8 + rq) * NUM_E + e];
            }
        }

        if (c == 0) {
            #pragma unroll
            for (int r = 0; r < 2; r++) {
                out[rowbase + r * 16 + rq]     = oa[r][0];
                out[rowbase + r * 16 + 8 + rq] = oa[r][1];
            }
        }
    }
}

extern "C" void kernel_launch(void* const* d_in, const int* in_sizes, int n_in,
                              void* d_out, int out_size) {
    const float* x     = (const float*)d_in[0];
    const float* probs = (const float*)d_in[1];
    const float* W1    = (const float*)d_in[2];
    const float* b1    = (const float*)d_in[3];
    const float* W2    = (const float*)d_in[4];
    const float* b2    = (const float*)d_in[5];
    const float* W3    = (const float*)d_in[6];
    const float* b3    = (const float*)d_in[7];
    float* out = (float*)d_out;

    const int B    = in_sizes[0] / 32;
    const int NT32 = B / 32;   // 16384 warp-tiles of 32 rows

    cudaFuncSetAttribute(moe_kernel, cudaFuncAttributeMaxDynamicSharedMemorySize, SMEM_BYTES);
    cudaFuncSetAttribute(moe_kernel, cudaFuncAttributePreferredSharedMemoryCarveout, 100);

    // 296 persistent CTAs (2 per SM), 2368 warps striding over 16384 tiles
    moe_kernel<<<296, 256, SMEM_BYTES>>>(x, probs, W1, b1, W2, b2, W3, b3, out, NT32);
}